// round 4
// baseline (speedup 1.0000x reference)
#include <cuda_runtime.h>
#include <math.h>
#include <stdint.h>

// Problem constants (fixed by dataset)
#define BB 8
#define NN 4096
#define CC 128
#define HH 256
#define KK 16
#define MM (BB * NN)   // 32768 rows

// Grid KNN parameters
#define GRD 32                   // cells per axis
#define NCELL (GRD * GRD * GRD)  // 32768
#define GLO (-5.0f)
#define GH  (10.0f / GRD)        // 0.3125
#define GINV (GRD / 10.0f)       // 3.2
#define CAP 64                   // bucket capacity (max cell count ~22)

// ---------------------------------------------------------------------------
// Scratch (device globals -> .bss, no allocation in kernel_launch)
// ---------------------------------------------------------------------------
__device__ float  g_asrc[MM * CC];
__device__ float  g_adst[MM * CC];
__device__ float  g_v[MM * CC];
__device__ float  g_acc[MM * CC];
__device__ int    g_idx[MM * KK];
__device__ int    g_cnt[BB * NCELL];
__device__ int    g_bucket[BB * NCELL * CAP];
__device__ float4 g_pos4[MM];

// ---------------------------------------------------------------------------
// Branch-free insert of (v, j) into a descending-sorted register array.
// Precondition: v < d[0].
// ---------------------------------------------------------------------------
__device__ __forceinline__ void sorted_insert16(float (&d)[KK], int (&id)[KK],
                                                float v, int j) {
    bool c_prev = true;
#pragma unroll
    for (int t = 0; t < KK - 1; t++) {
        const bool c_next = d[t + 1] > v;
        d[t]  = c_next ? d[t + 1]  : (c_prev ? v : d[t]);
        id[t] = c_next ? id[t + 1] : (c_prev ? j : id[t]);
        c_prev = c_next;
    }
    d[KK - 1]  = c_prev ? v : d[KK - 1];
    id[KK - 1] = c_prev ? j : id[KK - 1];
}

__device__ __forceinline__ int cell_coord(float p) {
    int c = (int)floorf((p - GLO) * GINV);
    return min(max(c, 0), GRD - 1);
}

// ---------------------------------------------------------------------------
// KNN kernels: zero counts, scatter into buckets, ring-expansion query.
// ---------------------------------------------------------------------------
__global__ void zero_counts() {
    const int i = blockIdx.x * blockDim.x + threadIdx.x;
    if (i < BB * NCELL) g_cnt[i] = 0;
}

__global__ void grid_build(const float* __restrict__ pos) {
    const int q = blockIdx.x * blockDim.x + threadIdx.x;   // global point
    if (q >= MM) return;
    const int b = q >> 12;            // q / NN
    const int i = q & (NN - 1);       // q % NN
    const float x = pos[q * 3 + 0];
    const float y = pos[q * 3 + 1];
    const float z = pos[q * 3 + 2];
    g_pos4[q] = make_float4(x, y, z, 0.0f);
    const int cell = (cell_coord(z) * GRD + cell_coord(y)) * GRD + cell_coord(x);
    const int slot = atomicAdd(&g_cnt[b * NCELL + cell], 1);
    if (slot < CAP) g_bucket[(b * NCELL + cell) * CAP + slot] = i;
}

__global__ void __launch_bounds__(128)
knn_query() {
    const int q = blockIdx.x * blockDim.x + threadIdx.x;
    if (q >= MM) return;
    const int b = q >> 12;
    const float4 p = g_pos4[q];

    const int cx = cell_coord(p.x);
    const int cy = cell_coord(p.y);
    const int cz = cell_coord(p.z);

    const float4* posb   = g_pos4 + b * NN;
    const int*    cntb   = g_cnt + b * NCELL;
    const int*    buckb  = g_bucket + b * NCELL * CAP;

    float d[KK];
    int   id[KK];
#pragma unroll
    for (int t = 0; t < KK; t++) { d[t] = 3.4e38f; id[t] = 0; }

    for (int r = 0; r < GRD; r++) {
        const int x0 = max(cx - r, 0), x1 = min(cx + r, GRD - 1);
        const int y0 = max(cy - r, 0), y1 = min(cy + r, GRD - 1);
        const int z0 = max(cz - r, 0), z1 = min(cz + r, GRD - 1);
        for (int z = z0; z <= z1; z++) {
            const int az = abs(z - cz);
            for (int y = y0; y <= y1; y++) {
                const int ay = abs(y - cy);
                const int m2 = max(az, ay);
                for (int x = x0; x <= x1; x++) {
                    if (max(m2, abs(x - cx)) != r) continue;   // shell only
                    const int cell = (z * GRD + y) * GRD + x;
                    const int cnt = min(cntb[cell], CAP);
                    const int* bk = buckb + cell * CAP;
                    for (int t = 0; t < cnt; t++) {
                        const int j = bk[t];
                        const float4 pj = posb[j];
                        const float dx = p.x - pj.x;
                        const float dy = p.y - pj.y;
                        const float dz = p.z - pj.z;
                        float d2 = dx * dx;
                        d2 = fmaf(dy, dy, d2);
                        d2 = fmaf(dz, dz, d2);
                        if (d2 < d[0]) sorted_insert16(d, id, d2, j);
                    }
                }
            }
        }
        // all unseen points (Chebyshev ring >= r+1) are at distance >= r*GH
        const float bound = (float)r * GH;
        if (d[0] <= bound * bound) break;
    }

    int* op = g_idx + q * KK;
#pragma unroll
    for (int t = 0; t < KK; t++) op[t] = id[t];
}

// ---------------------------------------------------------------------------
// GEMM core: C[M,N] = A[M,128] @ W[128,N] (+ bias)
// BM=128, BN=128, BK=8, 256 threads, 8x8 micro-tile (4+4 split halves).
// ---------------------------------------------------------------------------
template <bool BIAS>
__device__ __forceinline__ void gemm_body(
    const float* __restrict__ A, const float* __restrict__ W,
    const float* __restrict__ bias, float* __restrict__ Cout,
    int N, int bm, int bn) {
    __shared__ float As[8][128];
    __shared__ float Bs[8][128];

    const int tid = threadIdx.x;
    const int tx = tid & 15;
    const int ty = tid >> 4;

    float acc[8][8];
#pragma unroll
    for (int u = 0; u < 8; u++)
#pragma unroll
        for (int v = 0; v < 8; v++) acc[u][v] = 0.0f;

    const int ar = tid >> 1;
    const int ac4 = (tid & 1) * 4;
    const int wr = tid >> 5;
    const int wc = (tid & 31) * 4;

    for (int k0 = 0; k0 < 128; k0 += 8) {
        const float4 av = *(const float4*)&A[(size_t)(bm + ar) * 128 + k0 + ac4];
        const float4 wv = *(const float4*)&W[(size_t)(k0 + wr) * N + bn + wc];
        As[ac4 + 0][ar] = av.x;
        As[ac4 + 1][ar] = av.y;
        As[ac4 + 2][ar] = av.z;
        As[ac4 + 3][ar] = av.w;
        *(float4*)&Bs[wr][wc] = wv;
        __syncthreads();

#pragma unroll
        for (int kk = 0; kk < 8; kk++) {
            float a[8], bfr[8];
            *(float4*)&a[0]   = *(const float4*)&As[kk][ty * 4];
            *(float4*)&a[4]   = *(const float4*)&As[kk][64 + ty * 4];
            *(float4*)&bfr[0] = *(const float4*)&Bs[kk][tx * 4];
            *(float4*)&bfr[4] = *(const float4*)&Bs[kk][64 + tx * 4];
#pragma unroll
            for (int u = 0; u < 8; u++)
#pragma unroll
                for (int v = 0; v < 8; v++)
                    acc[u][v] = fmaf(a[u], bfr[v], acc[u][v]);
        }
        __syncthreads();
    }

#pragma unroll
    for (int hu = 0; hu < 2; hu++) {
#pragma unroll
        for (int u = 0; u < 4; u++) {
            const int row = bm + hu * 64 + ty * 4 + u;
            float* cp = &Cout[(size_t)row * N + bn];
#pragma unroll
            for (int hv = 0; hv < 2; hv++) {
                const int colb = hv * 64 + tx * 4;
                float4 r;
                r.x = acc[hu * 4 + u][hv * 4 + 0];
                r.y = acc[hu * 4 + u][hv * 4 + 1];
                r.z = acc[hu * 4 + u][hv * 4 + 2];
                r.w = acc[hu * 4 + u][hv * 4 + 3];
                if (BIAS) {
                    r.x += bias[bn + colb + 0];
                    r.y += bias[bn + colb + 1];
                    r.z += bias[bn + colb + 2];
                    r.w += bias[bn + colb + 3];
                }
                *(float4*)&cp[colb] = r;
            }
        }
    }
}

__global__ void __launch_bounds__(256, 2)
proj_kernel(const float* __restrict__ A,
            const float* __restrict__ Wsrc, const float* __restrict__ Wdst,
            const float* __restrict__ Wval,
            float* __restrict__ Osrc, float* __restrict__ Odst,
            float* __restrict__ Oval) {
    const float* W = (blockIdx.z == 0) ? Wsrc : (blockIdx.z == 1) ? Wdst : Wval;
    float* O       = (blockIdx.z == 0) ? Osrc : (blockIdx.z == 1) ? Odst : Oval;
    gemm_body<false>(A, W, nullptr, O, CC, blockIdx.x * 128, 0);
}

__global__ void __launch_bounds__(256, 2)
out_gemm_kernel(const float* __restrict__ A, const float* __restrict__ W,
                const float* __restrict__ bias, float* __restrict__ Cout) {
    gemm_body<true>(A, W, bias, Cout, HH, blockIdx.x * 128, blockIdx.y * 128);
}

// ---------------------------------------------------------------------------
// Attention: gather + per-(point,channel) softmax over 16 neighbors.
// One block (128 threads) per point; thread = channel. All offsets 32-bit.
// ---------------------------------------------------------------------------
__global__ void attn_kernel(const float* __restrict__ Wpos,
                            const float* __restrict__ bpos) {
    const int b = blockIdx.y;
    const int i = blockIdx.x;
    const int c = threadIdx.x;
    const int row = b * NN + i;   // < 32768

    __shared__ int   s_nbr[KK];
    __shared__ float s_rel[KK][3];

    if (c < KK) {
        const int j = g_idx[row * KK + c];
        s_nbr[c] = j;
        const float4 pi = g_pos4[row];
        const float4 pj = g_pos4[b * NN + j];
        s_rel[c][0] = pi.x - pj.x;
        s_rel[c][1] = pi.y - pj.y;
        s_rel[c][2] = pi.z - pj.z;
    }
    __syncthreads();

    const float w0 = Wpos[c];
    const float w1 = Wpos[128 + c];
    const float w2 = Wpos[256 + c];
    const float bp = bpos[c];

    const int basec = (b * NN) * CC + c;   // fits in int (max ~4.2M)
    const float adst = g_adst[row * CC + c];

    float alpha[KK], val[KK];
#pragma unroll
    for (int t = 0; t < KK; t++) {
        const int j = s_nbr[t];
        const int o = basec + j * CC;
        float delta = fmaf(s_rel[t][2], w2, bp);
        delta = fmaf(s_rel[t][1], w1, delta);
        delta = fmaf(s_rel[t][0], w0, delta);
        alpha[t] = adst - g_asrc[o] + delta;
        val[t]   = g_v[o] + delta;
    }

    float m = alpha[0];
#pragma unroll
    for (int t = 1; t < KK; t++) m = fmaxf(m, alpha[t]);

    float s = 0.0f, acc = 0.0f;
#pragma unroll
    for (int t = 0; t < KK; t++) {
        const float e = expf(alpha[t] - m);
        s += e;
        acc = fmaf(e, val[t], acc);
    }
    g_acc[row * CC + c] = acc / s;
}

// ---------------------------------------------------------------------------
// Launch
// ---------------------------------------------------------------------------
extern "C" void kernel_launch(void* const* d_in, const int* in_sizes, int n_in,
                              void* d_out, int out_size) {
    const float* x    = (const float*)d_in[0];
    const float* pos  = (const float*)d_in[1];
    const float* Wsrc = (const float*)d_in[2];
    const float* Wdst = (const float*)d_in[3];
    const float* Wval = (const float*)d_in[4];
    const float* Wpos = (const float*)d_in[5];
    const float* bpos = (const float*)d_in[6];
    const float* Wout = (const float*)d_in[7];
    const float* bout = (const float*)d_in[8];
    float* out = (float*)d_out;

    float *p_asrc, *p_adst, *p_v, *p_acc;
    cudaGetSymbolAddress((void**)&p_asrc, g_asrc);
    cudaGetSymbolAddress((void**)&p_adst, g_adst);
    cudaGetSymbolAddress((void**)&p_v,    g_v);
    cudaGetSymbolAddress((void**)&p_acc,  g_acc);

    // 1) grid KNN
    zero_counts<<<(BB * NCELL + 255) / 256, 256>>>();
    grid_build<<<(MM + 255) / 256, 256>>>(pos);
    knn_query<<<(MM + 127) / 128, 128>>>();

    // 2) projections: a_src, a_dst, v  (M=32768, K=128, N=128), fused over z
    proj_kernel<<<dim3(MM / 128, 1, 3), 256>>>(x, Wsrc, Wdst, Wval,
                                               p_asrc, p_adst, p_v);

    // 3) gather + softmax + weighted sum -> g_acc
    attn_kernel<<<dim3(NN, BB), 128>>>(Wpos, bpos);

    // 4) output projection: out = g_acc @ W_out + b_out  (N=256)
    out_gemm_kernel<<<dim3(MM / 128, HH / 128), 256>>>(p_acc, Wout, bout, out);
}

// round 5
// speedup vs baseline: 1.2768x; 1.2768x over previous
#include <cuda_runtime.h>
#include <math.h>
#include <stdint.h>

// Problem constants (fixed by dataset)
#define BB 8
#define NN 4096
#define CC 128
#define HH 256
#define KK 16
#define MM (BB * NN)   // 32768 rows

// Grid density parameters
#define GRD 32
#define NCELL (GRD * GRD * GRD)
#define GLO (-5.0f)
#define GH  (10.0f / GRD)        // 0.3125
#define GINV (GRD / 10.0f)       // 3.2

#define KNN_TILE 1024
#define BUF 64
// T = TSAFE * (TCOEF / n27)^(2/3);  TCOEF = 12*27*h^3/pi
#define TCOEF 3.1472f
#define TSAFE 1.7f

// ---------------------------------------------------------------------------
// Scratch (device globals -> .bss, no allocation in kernel_launch)
// ---------------------------------------------------------------------------
__device__ float  g_asrc[MM * CC];
__device__ float  g_adst[MM * CC];
__device__ float  g_v[MM * CC];
__device__ float  g_acc[MM * CC];
__device__ int    g_idx[MM * KK];
__device__ int    g_cnt[BB * NCELL];
__device__ float4 g_pos4[MM];

// ---------------------------------------------------------------------------
// Branch-free insert of (v, j) into a descending-sorted register array.
// Precondition: v < d[0]. Strict '<' -> earlier (lower-index) wins ties.
// ---------------------------------------------------------------------------
__device__ __forceinline__ void sorted_insert16(float (&d)[KK], int (&id)[KK],
                                                float v, int j) {
    bool c_prev = true;
#pragma unroll
    for (int t = 0; t < KK - 1; t++) {
        const bool c_next = d[t + 1] > v;
        d[t]  = c_next ? d[t + 1]  : (c_prev ? v : d[t]);
        id[t] = c_next ? id[t + 1] : (c_prev ? j : id[t]);
        c_prev = c_next;
    }
    d[KK - 1]  = c_prev ? v : d[KK - 1];
    id[KK - 1] = c_prev ? j : id[KK - 1];
}

__device__ __forceinline__ int cell_coord(float p) {
    int c = (int)floorf((p - GLO) * GINV);
    return min(max(c, 0), GRD - 1);
}

// Compact buffer to its exact top-16 (front slots); tighten T to 16th-best.
__device__ void compact16(float* bd, int* bi, int& cnt, float& T) {
    float d[KK]; int id[KK];
#pragma unroll
    for (int t = 0; t < KK; t++) { d[t] = 3.4e38f; id[t] = 0; }
    for (int t = 0; t < cnt; t++) {
        const float v = bd[t];
        if (v < d[0]) sorted_insert16(d, id, v, bi[t]);
    }
#pragma unroll
    for (int t = 0; t < KK; t++) { bd[t] = d[t]; bi[t] = id[t]; }
    cnt = KK;
    T = d[0];   // exact: nothing >= current 16th-best can enter top-16
}

// ---------------------------------------------------------------------------
// Grid build: per-cell counts only + pos cached as float4.
// ---------------------------------------------------------------------------
__global__ void zero_counts() {
    const int i = blockIdx.x * blockDim.x + threadIdx.x;
    if (i < BB * NCELL) g_cnt[i] = 0;
}

__global__ void grid_build(const float* __restrict__ pos) {
    const int q = blockIdx.x * blockDim.x + threadIdx.x;
    if (q >= MM) return;
    const int b = q >> 12;
    const float x = pos[q * 3 + 0];
    const float y = pos[q * 3 + 1];
    const float z = pos[q * 3 + 2];
    g_pos4[q] = make_float4(x, y, z, 0.0f);
    const int cell = (cell_coord(z) * GRD + cell_coord(y)) * GRD + cell_coord(x);
    atomicAdd(&g_cnt[b * NCELL + cell], 1);
}

// ---------------------------------------------------------------------------
// Threshold-filter KNN: exact top-16 via density-derived radius cutoff.
// Thread = query. Uniform control flow; append path is rare (~35/4096).
// ---------------------------------------------------------------------------
__global__ void __launch_bounds__(256)
knn_filter() {
    __shared__ float4 sp[KNN_TILE];   // 16 KB

    const int b = blockIdx.y;
    const int i = blockIdx.x * 256 + threadIdx.x;
    const int q = b * NN + i;
    const float4 p = g_pos4[q];

    // local density from 27 distinct (unclamped-duplicate-free) cells
    const int cx = cell_coord(p.x);
    const int cy = cell_coord(p.y);
    const int cz = cell_coord(p.z);
    int n27 = 0;
    const int* cntb = g_cnt + b * NCELL;
    for (int z = max(cz - 1, 0); z <= min(cz + 1, GRD - 1); z++)
        for (int y = max(cy - 1, 0); y <= min(cy + 1, GRD - 1); y++)
            for (int x = max(cx - 1, 0); x <= min(cx + 1, GRD - 1); x++)
                n27 += cntb[(z * GRD + y) * GRD + x];

    float T = TSAFE * powf(TCOEF / (float)n27, 0.6666667f);

    float buf_d[BUF];
    int   buf_i[BUF];
    int   cnt = 0;
    bool  done = false;

    const float4* posb = g_pos4 + b * NN;

    while (true) {
        for (int tile = 0; tile < NN; tile += KNN_TILE) {
            __syncthreads();
#pragma unroll
            for (int l = 0; l < KNN_TILE / 256; l++)
                sp[threadIdx.x + l * 256] = posb[tile + threadIdx.x + l * 256];
            __syncthreads();

            if (!done) {
#pragma unroll 4
                for (int j = 0; j < KNN_TILE; j++) {
                    const float4 pj = sp[j];
                    const float dx = p.x - pj.x;
                    const float dy = p.y - pj.y;
                    const float dz = p.z - pj.z;
                    float d2 = dx * dx;
                    d2 = fmaf(dy, dy, d2);
                    d2 = fmaf(dz, dz, d2);
                    if (d2 < T) {
                        if (cnt == BUF) compact16(buf_d, buf_i, cnt, T);
                        if (d2 < T) {   // re-check (T may have tightened)
                            buf_d[cnt] = d2;
                            buf_i[cnt] = tile + j;
                            cnt++;
                        }
                    }
                }
            }
        }
        if (!done) {
            if (cnt >= KK) done = true;
            else { T *= 3.0f; cnt = 0; }
        }
        if (!__syncthreads_or(!done)) break;
    }

    // exact top-16 from buffer
    float d[KK]; int id[KK];
#pragma unroll
    for (int t = 0; t < KK; t++) { d[t] = 3.4e38f; id[t] = 0; }
    for (int t = 0; t < cnt; t++) {
        const float v = buf_d[t];
        if (v < d[0]) sorted_insert16(d, id, v, buf_i[t]);
    }

    int* op = g_idx + q * KK;
#pragma unroll
    for (int t = 0; t < KK; t++) op[t] = id[t];
}

// ---------------------------------------------------------------------------
// GEMM core: C[M,N] = A[M,128] @ W[128,N] (+ bias)
// BM=128, BN=128, BK=8, 256 threads, 8x8 micro-tile (4+4 split halves).
// ---------------------------------------------------------------------------
template <bool BIAS>
__device__ __forceinline__ void gemm_body(
    const float* __restrict__ A, const float* __restrict__ W,
    const float* __restrict__ bias, float* __restrict__ Cout,
    int N, int bm, int bn) {
    __shared__ float As[8][128];
    __shared__ float Bs[8][128];

    const int tid = threadIdx.x;
    const int tx = tid & 15;
    const int ty = tid >> 4;

    float acc[8][8];
#pragma unroll
    for (int u = 0; u < 8; u++)
#pragma unroll
        for (int v = 0; v < 8; v++) acc[u][v] = 0.0f;

    const int ar = tid >> 1;
    const int ac4 = (tid & 1) * 4;
    const int wr = tid >> 5;
    const int wc = (tid & 31) * 4;

    for (int k0 = 0; k0 < 128; k0 += 8) {
        const float4 av = *(const float4*)&A[(size_t)(bm + ar) * 128 + k0 + ac4];
        const float4 wv = *(const float4*)&W[(size_t)(k0 + wr) * N + bn + wc];
        As[ac4 + 0][ar] = av.x;
        As[ac4 + 1][ar] = av.y;
        As[ac4 + 2][ar] = av.z;
        As[ac4 + 3][ar] = av.w;
        *(float4*)&Bs[wr][wc] = wv;
        __syncthreads();

#pragma unroll
        for (int kk = 0; kk < 8; kk++) {
            float a[8], bfr[8];
            *(float4*)&a[0]   = *(const float4*)&As[kk][ty * 4];
            *(float4*)&a[4]   = *(const float4*)&As[kk][64 + ty * 4];
            *(float4*)&bfr[0] = *(const float4*)&Bs[kk][tx * 4];
            *(float4*)&bfr[4] = *(const float4*)&Bs[kk][64 + tx * 4];
#pragma unroll
            for (int u = 0; u < 8; u++)
#pragma unroll
                for (int v = 0; v < 8; v++)
                    acc[u][v] = fmaf(a[u], bfr[v], acc[u][v]);
        }
        __syncthreads();
    }

#pragma unroll
    for (int hu = 0; hu < 2; hu++) {
#pragma unroll
        for (int u = 0; u < 4; u++) {
            const int row = bm + hu * 64 + ty * 4 + u;
            float* cp = &Cout[(size_t)row * N + bn];
#pragma unroll
            for (int hv = 0; hv < 2; hv++) {
                const int colb = hv * 64 + tx * 4;
                float4 r;
                r.x = acc[hu * 4 + u][hv * 4 + 0];
                r.y = acc[hu * 4 + u][hv * 4 + 1];
                r.z = acc[hu * 4 + u][hv * 4 + 2];
                r.w = acc[hu * 4 + u][hv * 4 + 3];
                if (BIAS) {
                    r.x += bias[bn + colb + 0];
                    r.y += bias[bn + colb + 1];
                    r.z += bias[bn + colb + 2];
                    r.w += bias[bn + colb + 3];
                }
                *(float4*)&cp[colb] = r;
            }
        }
    }
}

__global__ void __launch_bounds__(256, 2)
proj_kernel(const float* __restrict__ A,
            const float* __restrict__ Wsrc, const float* __restrict__ Wdst,
            const float* __restrict__ Wval,
            float* __restrict__ Osrc, float* __restrict__ Odst,
            float* __restrict__ Oval) {
    const float* W = (blockIdx.z == 0) ? Wsrc : (blockIdx.z == 1) ? Wdst : Wval;
    float* O       = (blockIdx.z == 0) ? Osrc : (blockIdx.z == 1) ? Odst : Oval;
    gemm_body<false>(A, W, nullptr, O, CC, blockIdx.x * 128, 0);
}

__global__ void __launch_bounds__(256, 2)
out_gemm_kernel(const float* __restrict__ A, const float* __restrict__ W,
                const float* __restrict__ bias, float* __restrict__ Cout) {
    gemm_body<true>(A, W, bias, Cout, HH, blockIdx.x * 128, blockIdx.y * 128);
}

// ---------------------------------------------------------------------------
// Attention: gather + per-(point,channel) softmax over 16 neighbors.
// One block (128 threads) per point; thread = channel. All offsets 32-bit.
// ---------------------------------------------------------------------------
__global__ void attn_kernel(const float* __restrict__ Wpos,
                            const float* __restrict__ bpos) {
    const int b = blockIdx.y;
    const int i = blockIdx.x;
    const int c = threadIdx.x;
    const int row = b * NN + i;

    __shared__ int   s_nbr[KK];
    __shared__ float s_rel[KK][3];

    if (c < KK) {
        const int j = g_idx[row * KK + c];
        s_nbr[c] = j;
        const float4 pi = g_pos4[row];
        const float4 pj = g_pos4[b * NN + j];
        s_rel[c][0] = pi.x - pj.x;
        s_rel[c][1] = pi.y - pj.y;
        s_rel[c][2] = pi.z - pj.z;
    }
    __syncthreads();

    const float w0 = Wpos[c];
    const float w1 = Wpos[128 + c];
    const float w2 = Wpos[256 + c];
    const float bp = bpos[c];

    const int basec = (b * NN) * CC + c;
    const float adst = g_adst[row * CC + c];

    float alpha[KK], val[KK];
#pragma unroll
    for (int t = 0; t < KK; t++) {
        const int j = s_nbr[t];
        const int o = basec + j * CC;
        float delta = fmaf(s_rel[t][2], w2, bp);
        delta = fmaf(s_rel[t][1], w1, delta);
        delta = fmaf(s_rel[t][0], w0, delta);
        alpha[t] = adst - g_asrc[o] + delta;
        val[t]   = g_v[o] + delta;
    }

    float m = alpha[0];
#pragma unroll
    for (int t = 1; t < KK; t++) m = fmaxf(m, alpha[t]);

    float s = 0.0f, acc = 0.0f;
#pragma unroll
    for (int t = 0; t < KK; t++) {
        const float e = expf(alpha[t] - m);
        s += e;
        acc = fmaf(e, val[t], acc);
    }
    g_acc[row * CC + c] = acc / s;
}

// ---------------------------------------------------------------------------
// Launch
// ---------------------------------------------------------------------------
extern "C" void kernel_launch(void* const* d_in, const int* in_sizes, int n_in,
                              void* d_out, int out_size) {
    const float* x    = (const float*)d_in[0];
    const float* pos  = (const float*)d_in[1];
    const float* Wsrc = (const float*)d_in[2];
    const float* Wdst = (const float*)d_in[3];
    const float* Wval = (const float*)d_in[4];
    const float* Wpos = (const float*)d_in[5];
    const float* bpos = (const float*)d_in[6];
    const float* Wout = (const float*)d_in[7];
    const float* bout = (const float*)d_in[8];
    float* out = (float*)d_out;

    float *p_asrc, *p_adst, *p_v, *p_acc;
    cudaGetSymbolAddress((void**)&p_asrc, g_asrc);
    cudaGetSymbolAddress((void**)&p_adst, g_adst);
    cudaGetSymbolAddress((void**)&p_v,    g_v);
    cudaGetSymbolAddress((void**)&p_acc,  g_acc);

    // 1) KNN: density grid + threshold-filter scan
    zero_counts<<<(BB * NCELL + 255) / 256, 256>>>();
    grid_build<<<(MM + 255) / 256, 256>>>(pos);
    knn_filter<<<dim3(NN / 256, BB), 256>>>();

    // 2) projections: a_src, a_dst, v  (M=32768, K=128, N=128), fused over z
    proj_kernel<<<dim3(MM / 128, 1, 3), 256>>>(x, Wsrc, Wdst, Wval,
                                               p_asrc, p_adst, p_v);

    // 3) gather + softmax + weighted sum -> g_acc
    attn_kernel<<<dim3(NN, BB), 128>>>(Wpos, bpos);

    // 4) output projection: out = g_acc @ W_out + b_out  (N=256)
    out_gemm_kernel<<<dim3(MM / 128, HH / 128), 256>>>(p_acc, Wout, bout, out);
}

// round 6
// speedup vs baseline: 3.4267x; 2.6839x over previous
#include <cuda_runtime.h>
#include <math.h>
#include <stdint.h>

// Problem constants (fixed by dataset)
#define BB 8
#define NN 4096
#define CC 128
#define HH 256
#define KK 16
#define MM (BB * NN)   // 32768 rows

// Grid density parameters
#define GRD 32
#define NCELL (GRD * GRD * GRD)
#define GLO (-5.0f)
#define GINV (GRD / 10.0f)       // 3.2

#define CAPW 160                 // per-warp candidate buffer

// ---------------------------------------------------------------------------
// Scratch (device globals -> .bss, no allocation in kernel_launch)
// ---------------------------------------------------------------------------
__device__ float  g_asrc[MM * CC];
__device__ float  g_adst[MM * CC];
__device__ float  g_v[MM * CC];
__device__ float  g_acc[MM * CC];
__device__ int    g_idx[MM * KK];
__device__ int    g_cnt[BB * NCELL];
__device__ float4 g_pos4[MM];

__device__ __forceinline__ int cell_coord(float p) {
    int c = (int)floorf((p - GLO) * GINV);
    return min(max(c, 0), GRD - 1);
}

// ---------------------------------------------------------------------------
// Grid build: per-cell counts + pos cached as float4.
// ---------------------------------------------------------------------------
__global__ void zero_counts() {
    const int i = blockIdx.x * blockDim.x + threadIdx.x;
    if (i < BB * NCELL) g_cnt[i] = 0;
}

__global__ void grid_build(const float* __restrict__ pos) {
    const int q = blockIdx.x * blockDim.x + threadIdx.x;
    if (q >= MM) return;
    const int b = q >> 12;
    const float x = pos[q * 3 + 0];
    const float y = pos[q * 3 + 1];
    const float z = pos[q * 3 + 2];
    g_pos4[q] = make_float4(x, y, z, 0.0f);
    const int cell = (cell_coord(z) * GRD + cell_coord(y)) * GRD + cell_coord(x);
    atomicAdd(&g_cnt[b * NCELL + cell], 1);
}

// ---------------------------------------------------------------------------
// Warp-cooperative threshold-filter KNN (exact).
// One warp per query: 32 lanes scan candidates in parallel; passers are
// ballot-compacted into a per-warp shared buffer; exact top-16 by ranking.
// All control flow is warp-uniform (T, cnt are warp-uniform).
// ---------------------------------------------------------------------------
__global__ void __launch_bounds__(256)
knn_warp() {
    __shared__ float sdbuf[8][CAPW];
    __shared__ int   sibuf[8][CAPW];

    const int wid  = threadIdx.x >> 5;
    const int lane = threadIdx.x & 31;
    const int b = blockIdx.y;
    const int q = blockIdx.x * 8 + wid;       // query index within batch
    const int gq = b * NN + q;

    float* wd = sdbuf[wid];
    int*   wi = sibuf[wid];

    const float4 p = g_pos4[gq];

    // --- local density from 27 neighbor cells (heuristic only; exactness
    //     comes from the retry loop) ---
    const int cx = cell_coord(p.x);
    const int cy = cell_coord(p.y);
    const int cz = cell_coord(p.z);
    int n27 = 0;
    if (lane < 27) {
        const int dz = lane / 9 - 1;
        const int dy = (lane / 3) % 3 - 1;
        const int dx = lane % 3 - 1;
        const int x = min(max(cx + dx, 0), GRD - 1);
        const int y = min(max(cy + dy, 0), GRD - 1);
        const int z = min(max(cz + dz, 0), GRD - 1);
        n27 = g_cnt[b * NCELL + (z * GRD + y) * GRD + x];
    }
#pragma unroll
    for (int o = 16; o; o >>= 1) n27 += __shfl_xor_sync(0xffffffffu, n27, o);

    // T such that expected in-ball count ~ 35 (=16 * 1.7^1.5)
    float T = 1.7f * powf(3.1472f / (float)n27, 0.6666667f);

    const float4* posb = g_pos4 + b * NN;
    const unsigned lmask = (1u << lane) - 1u;
    int cnt;

    while (true) {
        cnt = 0;
#pragma unroll 4
        for (int s = 0; s < NN; s += 32) {
            const float4 pj = posb[s + lane];
            const float dx = p.x - pj.x;
            const float dy = p.y - pj.y;
            const float dz = p.z - pj.z;
            float d2 = dx * dx;
            d2 = fmaf(dy, dy, d2);
            d2 = fmaf(dz, dz, d2);
            const bool pass = d2 < T;
            const unsigned m = __ballot_sync(0xffffffffu, pass);
            const int ofs = cnt + __popc(m & lmask);
            if (pass & (ofs < CAPW)) { wd[ofs] = d2; wi[ofs] = s + lane; }
            cnt += __popc(m);
        }
        if (cnt > CAPW)      T *= 0.5f;   // overflow: shrink (count ~ T^1.5)
        else if (cnt < KK)   T *= 3.0f;   // undershoot: grow
        else break;
    }

    // --- exact top-16 by ranking (lexicographic (d2, idx): matches top_k's
    //     lowest-index tie-break; strict total order -> ranks are unique) ---
    __syncwarp();
    for (int base = 0; base < cnt; base += 32) {
        const int l = base + lane;
        const bool have = l < cnt;
        const float dl = have ? wd[l] : 3.4e38f;
        const int   il = have ? wi[l] : 0x7fffffff;
        int rank = 0;
        for (int j = 0; j < cnt; j++) {
            const float dj = wd[j];
            const int   ij = wi[j];
            rank += (int)((dj < dl) | ((dj == dl) & (ij < il)));
        }
        if (have && rank < KK) g_idx[gq * KK + rank] = il;
    }
}

// ---------------------------------------------------------------------------
// GEMM core: C[M,N] = A[M,128] @ W[128,N] (+ bias)
// BM=128, BN=128, BK=8, 256 threads, 8x8 micro-tile (4+4 split halves).
// ---------------------------------------------------------------------------
template <bool BIAS>
__device__ __forceinline__ void gemm_body(
    const float* __restrict__ A, const float* __restrict__ W,
    const float* __restrict__ bias, float* __restrict__ Cout,
    int N, int bm, int bn) {
    __shared__ float As[8][128];
    __shared__ float Bs[8][128];

    const int tid = threadIdx.x;
    const int tx = tid & 15;
    const int ty = tid >> 4;

    float acc[8][8];
#pragma unroll
    for (int u = 0; u < 8; u++)
#pragma unroll
        for (int v = 0; v < 8; v++) acc[u][v] = 0.0f;

    const int ar = tid >> 1;
    const int ac4 = (tid & 1) * 4;
    const int wr = tid >> 5;
    const int wc = (tid & 31) * 4;

    for (int k0 = 0; k0 < 128; k0 += 8) {
        const float4 av = *(const float4*)&A[(size_t)(bm + ar) * 128 + k0 + ac4];
        const float4 wv = *(const float4*)&W[(size_t)(k0 + wr) * N + bn + wc];
        As[ac4 + 0][ar] = av.x;
        As[ac4 + 1][ar] = av.y;
        As[ac4 + 2][ar] = av.z;
        As[ac4 + 3][ar] = av.w;
        *(float4*)&Bs[wr][wc] = wv;
        __syncthreads();

#pragma unroll
        for (int kk = 0; kk < 8; kk++) {
            float a[8], bfr[8];
            *(float4*)&a[0]   = *(const float4*)&As[kk][ty * 4];
            *(float4*)&a[4]   = *(const float4*)&As[kk][64 + ty * 4];
            *(float4*)&bfr[0] = *(const float4*)&Bs[kk][tx * 4];
            *(float4*)&bfr[4] = *(const float4*)&Bs[kk][64 + tx * 4];
#pragma unroll
            for (int u = 0; u < 8; u++)
#pragma unroll
                for (int v = 0; v < 8; v++)
                    acc[u][v] = fmaf(a[u], bfr[v], acc[u][v]);
        }
        __syncthreads();
    }

#pragma unroll
    for (int hu = 0; hu < 2; hu++) {
#pragma unroll
        for (int u = 0; u < 4; u++) {
            const int row = bm + hu * 64 + ty * 4 + u;
            float* cp = &Cout[(size_t)row * N + bn];
#pragma unroll
            for (int hv = 0; hv < 2; hv++) {
                const int colb = hv * 64 + tx * 4;
                float4 r;
                r.x = acc[hu * 4 + u][hv * 4 + 0];
                r.y = acc[hu * 4 + u][hv * 4 + 1];
                r.z = acc[hu * 4 + u][hv * 4 + 2];
                r.w = acc[hu * 4 + u][hv * 4 + 3];
                if (BIAS) {
                    r.x += bias[bn + colb + 0];
                    r.y += bias[bn + colb + 1];
                    r.z += bias[bn + colb + 2];
                    r.w += bias[bn + colb + 3];
                }
                *(float4*)&cp[colb] = r;
            }
        }
    }
}

__global__ void __launch_bounds__(256, 2)
proj_kernel(const float* __restrict__ A,
            const float* __restrict__ Wsrc, const float* __restrict__ Wdst,
            const float* __restrict__ Wval,
            float* __restrict__ Osrc, float* __restrict__ Odst,
            float* __restrict__ Oval) {
    const float* W = (blockIdx.z == 0) ? Wsrc : (blockIdx.z == 1) ? Wdst : Wval;
    float* O       = (blockIdx.z == 0) ? Osrc : (blockIdx.z == 1) ? Odst : Oval;
    gemm_body<false>(A, W, nullptr, O, CC, blockIdx.x * 128, 0);
}

__global__ void __launch_bounds__(256, 2)
out_gemm_kernel(const float* __restrict__ A, const float* __restrict__ W,
                const float* __restrict__ bias, float* __restrict__ Cout) {
    gemm_body<true>(A, W, bias, Cout, HH, blockIdx.x * 128, blockIdx.y * 128);
}

// ---------------------------------------------------------------------------
// Attention: gather + per-(point,channel) softmax over 16 neighbors.
// One block (128 threads) per point; thread = channel. All offsets 32-bit.
// ---------------------------------------------------------------------------
__global__ void attn_kernel(const float* __restrict__ Wpos,
                            const float* __restrict__ bpos) {
    const int b = blockIdx.y;
    const int i = blockIdx.x;
    const int c = threadIdx.x;
    const int row = b * NN + i;

    __shared__ int   s_nbr[KK];
    __shared__ float s_rel[KK][3];

    if (c < KK) {
        const int j = g_idx[row * KK + c];
        s_nbr[c] = j;
        const float4 pi = g_pos4[row];
        const float4 pj = g_pos4[b * NN + j];
        s_rel[c][0] = pi.x - pj.x;
        s_rel[c][1] = pi.y - pj.y;
        s_rel[c][2] = pi.z - pj.z;
    }
    __syncthreads();

    const float w0 = Wpos[c];
    const float w1 = Wpos[128 + c];
    const float w2 = Wpos[256 + c];
    const float bp = bpos[c];

    const int basec = (b * NN) * CC + c;
    const float adst = g_adst[row * CC + c];

    float alpha[KK], val[KK];
#pragma unroll
    for (int t = 0; t < KK; t++) {
        const int j = s_nbr[t];
        const int o = basec + j * CC;
        float delta = fmaf(s_rel[t][2], w2, bp);
        delta = fmaf(s_rel[t][1], w1, delta);
        delta = fmaf(s_rel[t][0], w0, delta);
        alpha[t] = adst - g_asrc[o] + delta;
        val[t]   = g_v[o] + delta;
    }

    float m = alpha[0];
#pragma unroll
    for (int t = 1; t < KK; t++) m = fmaxf(m, alpha[t]);

    float s = 0.0f, acc = 0.0f;
#pragma unroll
    for (int t = 0; t < KK; t++) {
        const float e = expf(alpha[t] - m);
        s += e;
        acc = fmaf(e, val[t], acc);
    }
    g_acc[row * CC + c] = acc / s;
}

// ---------------------------------------------------------------------------
// Launch
// ---------------------------------------------------------------------------
extern "C" void kernel_launch(void* const* d_in, const int* in_sizes, int n_in,
                              void* d_out, int out_size) {
    const float* x    = (const float*)d_in[0];
    const float* pos  = (const float*)d_in[1];
    const float* Wsrc = (const float*)d_in[2];
    const float* Wdst = (const float*)d_in[3];
    const float* Wval = (const float*)d_in[4];
    const float* Wpos = (const float*)d_in[5];
    const float* bpos = (const float*)d_in[6];
    const float* Wout = (const float*)d_in[7];
    const float* bout = (const float*)d_in[8];
    float* out = (float*)d_out;

    float *p_asrc, *p_adst, *p_v, *p_acc;
    cudaGetSymbolAddress((void**)&p_asrc, g_asrc);
    cudaGetSymbolAddress((void**)&p_adst, g_adst);
    cudaGetSymbolAddress((void**)&p_v,    g_v);
    cudaGetSymbolAddress((void**)&p_acc,  g_acc);

    // 1) KNN: density grid + warp-cooperative threshold filter
    zero_counts<<<(BB * NCELL + 255) / 256, 256>>>();
    grid_build<<<(MM + 255) / 256, 256>>>(pos);
    knn_warp<<<dim3(NN / 8, BB), 256>>>();

    // 2) projections: a_src, a_dst, v  (M=32768, K=128, N=128), fused over z
    proj_kernel<<<dim3(MM / 128, 1, 3), 256>>>(x, Wsrc, Wdst, Wval,
                                               p_asrc, p_adst, p_v);

    // 3) gather + softmax + weighted sum -> g_acc
    attn_kernel<<<dim3(NN, BB), 128>>>(Wpos, bpos);

    // 4) output projection: out = g_acc @ W_out + b_out  (N=256)
    out_gemm_kernel<<<dim3(MM / 128, HH / 128), 256>>>(p_acc, Wout, bout, out);
}

// round 8
// speedup vs baseline: 3.5346x; 1.0315x over previous
#include <cuda_runtime.h>
#include <math.h>
#include <stdint.h>

typedef unsigned long long ull;

// Problem constants (fixed by dataset)
#define BB 8
#define NN 4096
#define CC 128
#define HH 256
#define KK 16
#define MM (BB * NN)   // 32768 rows

// Grid density parameters
#define GRD 32
#define NCELL (GRD * GRD * GRD)
#define GLO (-5.0f)
#define GINV (GRD / 10.0f)       // 3.2

#define CAPW 160                 // per-warp candidate buffer

// Packed fp32x2 FMA (Blackwell FFMA2; ptxas never emits it from C++)
#define FMA_F32X2(d, a, b, c) \
    asm("fma.rn.f32x2 %0, %1, %2, %3;" : "=l"(d) : "l"(a), "l"(b), "l"(c))
#define PACK_DUP_F32X2(out, v) \
    asm("mov.b64 %0, {%1, %1};" : "=l"(out) : "r"(__float_as_uint(v)))

// ---------------------------------------------------------------------------
// Scratch (device globals -> .bss, no allocation in kernel_launch)
// ---------------------------------------------------------------------------
__device__ float  g_asrc[MM * CC];
__device__ float  g_adst[MM * CC];
__device__ float  g_v[MM * CC];
__device__ float  g_acc[MM * CC];
__device__ int    g_idx[MM * KK];
__device__ int    g_cnt[BB * NCELL];
__device__ float4 g_pos4[MM];

__device__ __forceinline__ int cell_coord(float p) {
    int c = (int)floorf((p - GLO) * GINV);
    return min(max(c, 0), GRD - 1);
}

// ---------------------------------------------------------------------------
// Grid build: per-cell counts + pos cached as float4.
// ---------------------------------------------------------------------------
__global__ void zero_counts() {
    const int i = blockIdx.x * blockDim.x + threadIdx.x;
    if (i < BB * NCELL) g_cnt[i] = 0;
}

__global__ void grid_build(const float* __restrict__ pos) {
    const int q = blockIdx.x * blockDim.x + threadIdx.x;
    if (q >= MM) return;
    const int b = q >> 12;
    const float x = pos[q * 3 + 0];
    const float y = pos[q * 3 + 1];
    const float z = pos[q * 3 + 2];
    g_pos4[q] = make_float4(x, y, z, 0.0f);
    const int cell = (cell_coord(z) * GRD + cell_coord(y)) * GRD + cell_coord(x);
    atomicAdd(&g_cnt[b * NCELL + cell], 1);
}

// ---------------------------------------------------------------------------
// Warp-cooperative threshold-filter KNN (exact). One warp per query.
// ---------------------------------------------------------------------------
__global__ void __launch_bounds__(256)
knn_warp() {
    __shared__ float sdbuf[8][CAPW];
    __shared__ int   sibuf[8][CAPW];

    const int wid  = threadIdx.x >> 5;
    const int lane = threadIdx.x & 31;
    const int b = blockIdx.y;
    const int q = blockIdx.x * 8 + wid;
    const int gq = b * NN + q;

    float* wd = sdbuf[wid];
    int*   wi = sibuf[wid];

    const float4 p = g_pos4[gq];

    const int cx = cell_coord(p.x);
    const int cy = cell_coord(p.y);
    const int cz = cell_coord(p.z);
    int n27 = 0;
    if (lane < 27) {
        const int dz = lane / 9 - 1;
        const int dy = (lane / 3) % 3 - 1;
        const int dx = lane % 3 - 1;
        const int x = min(max(cx + dx, 0), GRD - 1);
        const int y = min(max(cy + dy, 0), GRD - 1);
        const int z = min(max(cz + dz, 0), GRD - 1);
        n27 = g_cnt[b * NCELL + (z * GRD + y) * GRD + x];
    }
#pragma unroll
    for (int o = 16; o; o >>= 1) n27 += __shfl_xor_sync(0xffffffffu, n27, o);

    float T = 1.7f * powf(3.1472f / (float)n27, 0.6666667f);

    const float4* posb = g_pos4 + b * NN;
    const unsigned lmask = (1u << lane) - 1u;
    int cnt;

    while (true) {
        cnt = 0;
#pragma unroll 4
        for (int s = 0; s < NN; s += 32) {
            const float4 pj = posb[s + lane];
            const float dx = p.x - pj.x;
            const float dy = p.y - pj.y;
            const float dz = p.z - pj.z;
            float d2 = dx * dx;
            d2 = fmaf(dy, dy, d2);
            d2 = fmaf(dz, dz, d2);
            const bool pass = d2 < T;
            const unsigned m = __ballot_sync(0xffffffffu, pass);
            const int ofs = cnt + __popc(m & lmask);
            if (pass & (ofs < CAPW)) { wd[ofs] = d2; wi[ofs] = s + lane; }
            cnt += __popc(m);
        }
        if (cnt > CAPW)      T *= 0.5f;
        else if (cnt < KK)   T *= 3.0f;
        else break;
    }

    __syncwarp();
    for (int base = 0; base < cnt; base += 32) {
        const int l = base + lane;
        const bool have = l < cnt;
        const float dl = have ? wd[l] : 3.4e38f;
        const int   il = have ? wi[l] : 0x7fffffff;
        int rank = 0;
        for (int j = 0; j < cnt; j++) {
            const float dj = wd[j];
            const int   ij = wi[j];
            rank += (int)((dj < dl) | ((dj == dl) & (ij < il)));
        }
        if (have && rank < KK) g_idx[gq * KK + rank] = il;
    }
}

// ---------------------------------------------------------------------------
// GEMM core: C[M,N] = A[M,128] @ W[128,N] (+ bias)
// BM=128, BN=128, BK=8, 256 threads, 8x8 micro-tile via packed FFMA2
// (8x4 f32x2 accumulators). Bit-identical to scalar fp32 FMA.
// ---------------------------------------------------------------------------
template <bool BIAS>
__device__ __forceinline__ void gemm_body(
    const float* __restrict__ A, const float* __restrict__ W,
    const float* __restrict__ bias, float* __restrict__ Cout,
    int N, int bm, int bn) {
    __shared__ float As[8][128];
    __shared__ float Bs[8][128];

    const int tid = threadIdx.x;
    const int tx = tid & 15;
    const int ty = tid >> 4;

    ull acc2[8][4];
#pragma unroll
    for (int u = 0; u < 8; u++)
#pragma unroll
        for (int v = 0; v < 4; v++) acc2[u][v] = 0ull;

    const int ar = tid >> 1;
    const int ac4 = (tid & 1) * 4;
    const int wr = tid >> 5;
    const int wc = (tid & 31) * 4;

    for (int k0 = 0; k0 < 128; k0 += 8) {
        const float4 av = *(const float4*)&A[(size_t)(bm + ar) * 128 + k0 + ac4];
        const float4 wv = *(const float4*)&W[(size_t)(k0 + wr) * N + bn + wc];
        As[ac4 + 0][ar] = av.x;
        As[ac4 + 1][ar] = av.y;
        As[ac4 + 2][ar] = av.z;
        As[ac4 + 3][ar] = av.w;
        *(float4*)&Bs[wr][wc] = wv;
        __syncthreads();

#pragma unroll
        for (int kk = 0; kk < 8; kk++) {
            float a[8];
            *(float4*)&a[0] = *(const float4*)&As[kk][ty * 4];
            *(float4*)&a[4] = *(const float4*)&As[kk][64 + ty * 4];
            ull b2[4];
            b2[0] = *(const ull*)&Bs[kk][tx * 4];
            b2[1] = *(const ull*)&Bs[kk][tx * 4 + 2];
            b2[2] = *(const ull*)&Bs[kk][64 + tx * 4];
            b2[3] = *(const ull*)&Bs[kk][64 + tx * 4 + 2];
#pragma unroll
            for (int u = 0; u < 8; u++) {
                ull a2;
                PACK_DUP_F32X2(a2, a[u]);
#pragma unroll
                for (int v = 0; v < 4; v++)
                    FMA_F32X2(acc2[u][v], a2, b2[v], acc2[u][v]);
            }
        }
        __syncthreads();
    }

#pragma unroll
    for (int hu = 0; hu < 2; hu++) {
#pragma unroll
        for (int u = 0; u < 4; u++) {
            const int row = bm + hu * 64 + ty * 4 + u;
            float* cp = &Cout[(size_t)row * N + bn];
#pragma unroll
            for (int hv = 0; hv < 2; hv++) {
                const int colb = hv * 64 + tx * 4;
                float2 lo = *(float2*)&acc2[hu * 4 + u][hv * 2 + 0];
                float2 hi = *(float2*)&acc2[hu * 4 + u][hv * 2 + 1];
                float4 r;
                r.x = lo.x; r.y = lo.y; r.z = hi.x; r.w = hi.y;
                if (BIAS) {
                    r.x += bias[bn + colb + 0];
                    r.y += bias[bn + colb + 1];
                    r.z += bias[bn + colb + 2];
                    r.w += bias[bn + colb + 3];
                }
                *(float4*)&cp[colb] = r;
            }
        }
    }
}

__global__ void __launch_bounds__(256, 2)
proj_kernel(const float* __restrict__ A,
            const float* __restrict__ Wsrc, const float* __restrict__ Wdst,
            const float* __restrict__ Wval,
            float* __restrict__ Osrc, float* __restrict__ Odst,
            float* __restrict__ Oval) {
    const float* W = (blockIdx.z == 0) ? Wsrc : (blockIdx.z == 1) ? Wdst : Wval;
    float* O       = (blockIdx.z == 0) ? Osrc : (blockIdx.z == 1) ? Odst : Oval;
    gemm_body<false>(A, W, nullptr, O, CC, blockIdx.x * 128, 0);
}

__global__ void __launch_bounds__(256, 2)
out_gemm_kernel(const float* __restrict__ A, const float* __restrict__ W,
                const float* __restrict__ bias, float* __restrict__ Cout) {
    gemm_body<true>(A, W, bias, Cout, HH, blockIdx.x * 128, blockIdx.y * 128);
}

// ---------------------------------------------------------------------------
// Attention: 4 points per 256-block, 64 threads/point, 2 channels/thread
// (float2 gathers). Per-channel softmax over 16 neighbors; __expf.
// ---------------------------------------------------------------------------
__global__ void __launch_bounds__(256)
attn_kernel(const float* __restrict__ Wpos, const float* __restrict__ bpos) {
    const int sub = threadIdx.x >> 6;       // 0..3 point within block
    const int c2  = threadIdx.x & 63;       // channel pair
    const int b = blockIdx.y;
    const int i = blockIdx.x * 4 + sub;
    const int row = b * NN + i;
    const int c = c2 * 2;

    __shared__ int   s_nbr[4][KK];
    __shared__ float s_rel[4][KK][3];

    if (c2 < KK) {
        const int j = g_idx[row * KK + c2];
        s_nbr[sub][c2] = j;
        const float4 pi = g_pos4[row];
        const float4 pj = g_pos4[b * NN + j];
        s_rel[sub][c2][0] = pi.x - pj.x;
        s_rel[sub][c2][1] = pi.y - pj.y;
        s_rel[sub][c2][2] = pi.z - pj.z;
    }
    __syncthreads();

    const float2 w0 = *(const float2*)&Wpos[c];
    const float2 w1 = *(const float2*)&Wpos[128 + c];
    const float2 w2 = *(const float2*)&Wpos[256 + c];
    const float2 bp = *(const float2*)&bpos[c];

    const int basec = (b * NN) * CC + c;
    const float2 adst = *(const float2*)&g_adst[row * CC + c];

    float2 alpha[KK], val[KK];
#pragma unroll
    for (int t = 0; t < KK; t++) {
        const int j = s_nbr[sub][t];
        const int o = basec + j * CC;
        const float r0 = s_rel[sub][t][0];
        const float r1 = s_rel[sub][t][1];
        const float r2 = s_rel[sub][t][2];
        float dx_ = fmaf(r2, w2.x, bp.x);
        dx_ = fmaf(r1, w1.x, dx_);
        dx_ = fmaf(r0, w0.x, dx_);
        float dy_ = fmaf(r2, w2.y, bp.y);
        dy_ = fmaf(r1, w1.y, dy_);
        dy_ = fmaf(r0, w0.y, dy_);
        const float2 as = *(const float2*)&g_asrc[o];
        const float2 vv = *(const float2*)&g_v[o];
        alpha[t].x = adst.x - as.x + dx_;
        alpha[t].y = adst.y - as.y + dy_;
        val[t].x = vv.x + dx_;
        val[t].y = vv.y + dy_;
    }

    float mx = alpha[0].x, my = alpha[0].y;
#pragma unroll
    for (int t = 1; t < KK; t++) {
        mx = fmaxf(mx, alpha[t].x);
        my = fmaxf(my, alpha[t].y);
    }

    float sx = 0.f, sy = 0.f, ax = 0.f, ay = 0.f;
#pragma unroll
    for (int t = 0; t < KK; t++) {
        const float ex = __expf(alpha[t].x - mx);
        const float ey = __expf(alpha[t].y - my);
        sx += ex; sy += ey;
        ax = fmaf(ex, val[t].x, ax);
        ay = fmaf(ey, val[t].y, ay);
    }
    float2 r;
    r.x = __fdividef(ax, sx);
    r.y = __fdividef(ay, sy);
    *(float2*)&g_acc[row * CC + c] = r;
}

// ---------------------------------------------------------------------------
// Launch
// ---------------------------------------------------------------------------
extern "C" void kernel_launch(void* const* d_in, const int* in_sizes, int n_in,
                              void* d_out, int out_size) {
    const float* x    = (const float*)d_in[0];
    const float* pos  = (const float*)d_in[1];
    const float* Wsrc = (const float*)d_in[2];
    const float* Wdst = (const float*)d_in[3];
    const float* Wval = (const float*)d_in[4];
    const float* Wpos = (const float*)d_in[5];
    const float* bpos = (const float*)d_in[6];
    const float* Wout = (const float*)d_in[7];
    const float* bout = (const float*)d_in[8];
    float* out = (float*)d_out;

    float *p_asrc, *p_adst, *p_v, *p_acc;
    cudaGetSymbolAddress((void**)&p_asrc, g_asrc);
    cudaGetSymbolAddress((void**)&p_adst, g_adst);
    cudaGetSymbolAddress((void**)&p_v,    g_v);
    cudaGetSymbolAddress((void**)&p_acc,  g_acc);

    // 1) KNN: density grid + warp-cooperative threshold filter
    zero_counts<<<(BB * NCELL + 255) / 256, 256>>>();
    grid_build<<<(MM + 255) / 256, 256>>>(pos);
    knn_warp<<<dim3(NN / 8, BB), 256>>>();

    // 2) projections: a_src, a_dst, v  (M=32768, K=128, N=128), fused over z
    proj_kernel<<<dim3(MM / 128, 1, 3), 256>>>(x, Wsrc, Wdst, Wval,
                                               p_asrc, p_adst, p_v);

    // 3) gather + softmax + weighted sum -> g_acc
    attn_kernel<<<dim3(NN / 4, BB), 256>>>(Wpos, bpos);

    // 4) output projection: out = g_acc @ W_out + b_out  (N=256)
    out_gemm_kernel<<<dim3(MM / 128, HH / 128), 256>>>(p_acc, Wout, bout, out);
}